// round 2
// baseline (speedup 1.0000x reference)
#include <cuda_runtime.h>
#include <math.h>

// Problem dimensions (fixed by the dataset)
#define N_ANCHOR 1000
#define PDIM     100000
#define BDIM     256

// GEMM tiling
#define BM 64
#define BN 64
#define BK 16

#define EPI_PLAIN 0
#define EPI_SYM   1
#define EPI_CLAMP 2

#define NEWTON_ITERS 10

// ---------------- scratch (device globals; no allocation allowed) ----------
__device__ float g_S [N_ANCHOR * N_ANCHOR];
__device__ float g_Z [N_ANCHOR * N_ANCHOR];
__device__ float g_Z2[N_ANCHOR * N_ANCHOR];
__device__ float g_U [N_ANCHOR * N_ANCHOR];
__device__ float g_Cm[BDIM * N_ANCHOR];
__device__ float g_X [BDIM * N_ANCHOR];
__device__ float g_E [BDIM * N_ANCHOR];
__device__ float g_X2[BDIM * N_ANCHOR];
__device__ float g_rowsum[N_ANCHOR];
__device__ float g_invb;
__device__ float g_scale[BDIM];

// ---------------------------------------------------------------------------
// Generic tiled SGEMM, arbitrary M/N/K (k-tail handled with guards).
//   TB = true : C[M,N] = A[M,K] * B[N,K]^T        (both row-major, contract cols)
//   TB = false: C[M,N] = A[M,K] * B[K,N]
// Epilogue modes:
//   EPI_PLAIN: C = alpha*acc (+ beta*D)
//   EPI_SYM  : square symmetric output; only lower-tri blocks computed, mirrored
//   EPI_CLAMP: out = scale[m]*acc + clamp(priv[m,n] - acc, +-1e-3)
// ---------------------------------------------------------------------------
template <bool TB>
__global__ void __launch_bounds__(256)
gemm_k(const float* __restrict__ A, const float* __restrict__ B,
       float* __restrict__ C, int M, int N, int K,
       float alpha, const float* __restrict__ D, float beta,
       int mode, const float* __restrict__ priv, const float* __restrict__ scale)
{
    const int bx = blockIdx.x, by = blockIdx.y;
    if (mode == EPI_SYM && bx > by) return;  // upper-tri blocks filled by mirror

    const int n0 = bx * BN;
    const int m0 = by * BM;
    const int tx = threadIdx.x, ty = threadIdx.y;
    const int tid = ty * 16 + tx;

    __shared__ float As[BK][BM];
    __shared__ float Bs[BK][BN];

    float acc[4][4] = {};

    const int am  = tid >> 2;          // 0..63  (row within tile)
    const int ak  = (tid & 3) << 2;    // 0,4,8,12 (k within tile, vec4)
    const int bk  = tid >> 4;          // 0..15  (NN: k within tile)
    const int bn4 = (tid & 15) << 2;   // 0..60  (NN: col within tile, vec4)

    for (int k0 = 0; k0 < K; k0 += BK) {
        // ---- load A tile (vec4 along K, store transposed), k-guarded ----
        {
            float4 av = make_float4(0.f, 0.f, 0.f, 0.f);
            if (m0 + am < M) {
                const float* Arow = &A[(size_t)(m0 + am) * K + k0 + ak];
                if (k0 + ak + 3 < K) {
                    av = *(const float4*)Arow;
                } else {
                    float t[4] = {0.f, 0.f, 0.f, 0.f};
                    #pragma unroll
                    for (int j = 0; j < 4; j++)
                        if (k0 + ak + j < K) t[j] = Arow[j];
                    av = make_float4(t[0], t[1], t[2], t[3]);
                }
            }
            As[ak + 0][am] = av.x; As[ak + 1][am] = av.y;
            As[ak + 2][am] = av.z; As[ak + 3][am] = av.w;
        }

        // ---- load B tile, k-guarded ----
        if (TB) {
            float4 bv = make_float4(0.f, 0.f, 0.f, 0.f);
            if (n0 + am < N) {
                const float* Brow = &B[(size_t)(n0 + am) * K + k0 + ak];
                if (k0 + ak + 3 < K) {
                    bv = *(const float4*)Brow;
                } else {
                    float t[4] = {0.f, 0.f, 0.f, 0.f};
                    #pragma unroll
                    for (int j = 0; j < 4; j++)
                        if (k0 + ak + j < K) t[j] = Brow[j];
                    bv = make_float4(t[0], t[1], t[2], t[3]);
                }
            }
            Bs[ak + 0][am] = bv.x; Bs[ak + 1][am] = bv.y;
            Bs[ak + 2][am] = bv.z; Bs[ak + 3][am] = bv.w;
        } else {
            if (k0 + bk < K) {
                const float* Brow = &B[(size_t)(k0 + bk) * N + n0 + bn4];
                if (n0 + bn4 + 3 < N) {
                    *(float4*)&Bs[bk][bn4] = *(const float4*)Brow;
                } else {
                    #pragma unroll
                    for (int j = 0; j < 4; j++)
                        Bs[bk][bn4 + j] = (n0 + bn4 + j < N) ? Brow[j] : 0.f;
                }
            } else {
                *(float4*)&Bs[bk][bn4] = make_float4(0.f, 0.f, 0.f, 0.f);
            }
        }
        __syncthreads();

        // ---- compute ----
        #pragma unroll
        for (int k = 0; k < BK; k++) {
            float4 a = *(const float4*)&As[k][ty << 2];
            float4 b = *(const float4*)&Bs[k][tx << 2];
            float ar[4] = {a.x, a.y, a.z, a.w};
            float br[4] = {b.x, b.y, b.z, b.w};
            #pragma unroll
            for (int i = 0; i < 4; i++)
                #pragma unroll
                for (int j = 0; j < 4; j++)
                    acc[i][j] = fmaf(ar[i], br[j], acc[i][j]);
        }
        __syncthreads();
    }

    // ---- epilogue ----
    #pragma unroll
    for (int i = 0; i < 4; i++) {
        const int m = m0 + (ty << 2) + i;
        if (m >= M) continue;
        #pragma unroll
        for (int j = 0; j < 4; j++) {
            const int n = n0 + (tx << 2) + j;
            if (n >= N) continue;
            const float t = acc[i][j];
            float v;
            if (mode == EPI_CLAMP) {
                float r = priv[(size_t)m * N + n] - t;
                r = fminf(fmaxf(r, -1e-3f), 1e-3f);
                v = scale[m] * t + r;
            } else {
                v = alpha * t;
                if (D) v += beta * D[(size_t)m * N + n];
            }
            C[(size_t)m * N + n] = v;
            if (mode == EPI_SYM)
                C[(size_t)n * N + m] = v;   // mirror (bitwise-consistent on diag)
        }
    }
}

// ---------------- small helper kernels -------------------------------------
__global__ void rowsum_abs_k(int n)
{
    const int i = blockIdx.x;
    float s = 0.f;
    for (int j = threadIdx.x; j < n; j += blockDim.x) s += fabsf(g_S[i * n + j]);
    __shared__ float sh[256];
    sh[threadIdx.x] = s; __syncthreads();
    for (int o = 128; o > 0; o >>= 1) {
        if (threadIdx.x < o) sh[threadIdx.x] += sh[threadIdx.x + o];
        __syncthreads();
    }
    if (threadIdx.x == 0) g_rowsum[i] = sh[0];
}

__global__ void maxinv_k(int n)
{
    float m = 0.f;
    for (int j = threadIdx.x; j < n; j += blockDim.x) m = fmaxf(m, g_rowsum[j]);
    __shared__ float sh[256];
    sh[threadIdx.x] = m; __syncthreads();
    for (int o = 128; o > 0; o >>= 1) {
        if (threadIdx.x < o) sh[threadIdx.x] = fmaxf(sh[threadIdx.x], sh[threadIdx.x + o]);
        __syncthreads();
    }
    if (threadIdx.x == 0) g_invb = 1.0f / sh[0];
}

__global__ void initZ_k(int n)
{
    const int idx = blockIdx.x * blockDim.x + threadIdx.x;
    if (idx < n * n) {
        const int i = idx / n, j = idx % n;
        g_Z[idx] = (i == j) ? g_invb : 0.f;
    }
}

__global__ void scale_k(int n)
{
    const int i = blockIdx.x;
    float s = 0.f;
    for (int j = threadIdx.x; j < n; j += blockDim.x)
        s += g_X2[i * n + j] * g_Cm[i * n + j];   // = ||P_S priv_i||^2
    __shared__ float sh[256];
    sh[threadIdx.x] = s; __syncthreads();
    for (int o = 128; o > 0; o >>= 1) {
        if (threadIdx.x < o) sh[threadIdx.x] += sh[threadIdx.x + o];
        __syncthreads();
    }
    if (threadIdx.x == 0) {
        const float d = fmaxf(sh[0], 1e-30f);
        g_scale[i] = fminf(1.0f / sqrtf(d), 1.0f);   // CLIP = 1.0
    }
}

// ---------------------------------------------------------------------------
extern "C" void kernel_launch(void* const* d_in, const int* in_sizes, int n_in,
                              void* d_out, int out_size)
{
    const float* pub  = (const float*)d_in[0];   // [1000, 100000]
    const float* priv = (const float*)d_in[1];   // [256, 100000]
    // d_in[2] (L_init) and d_in[3] (power_iter) are mathematically irrelevant:
    // for power_iter >= 1 the output depends only on rowspace(pub_grad).
    float* out = (float*)d_out;                  // [256, 100000]

    float *S, *Z, *Z2, *U, *Cm, *X, *E, *X2, *scale;
    cudaGetSymbolAddress((void**)&S,  g_S);
    cudaGetSymbolAddress((void**)&Z,  g_Z);
    cudaGetSymbolAddress((void**)&Z2, g_Z2);
    cudaGetSymbolAddress((void**)&U,  g_U);
    cudaGetSymbolAddress((void**)&Cm, g_Cm);
    cudaGetSymbolAddress((void**)&X,  g_X);
    cudaGetSymbolAddress((void**)&E,  g_E);
    cudaGetSymbolAddress((void**)&X2, g_X2);
    cudaGetSymbolAddress((void**)&scale, g_scale);

    const dim3 tb(16, 16);

    // 1) S = pub * pub^T  (symmetric: lower-tri blocks + mirror)
    {
        dim3 g((N_ANCHOR + BN - 1) / BN, (N_ANCHOR + BM - 1) / BM);
        gemm_k<true><<<g, tb>>>(pub, pub, S, N_ANCHOR, N_ANCHOR, PDIM,
                                1.f, nullptr, 0.f, EPI_SYM, nullptr, nullptr);
    }

    // 2) spectral bound + Z0 = I / ||S||_1
    rowsum_abs_k<<<N_ANCHOR, 256>>>(N_ANCHOR);
    maxinv_k<<<1, 256>>>(N_ANCHOR);
    initZ_k<<<(N_ANCHOR * N_ANCHOR + 255) / 256, 256>>>(N_ANCHOR);

    // 3) Newton-Schulz: Z <- Z (2I - S Z)   (quadratic; kappa(S) ~ 1.5)
    {
        dim3 g((N_ANCHOR + BN - 1) / BN, (N_ANCHOR + BM - 1) / BM);
        float* Zc = Z;
        float* Za = Z2;
        for (int t = 0; t < NEWTON_ITERS; t++) {
            gemm_k<false><<<g, tb>>>(S, Zc, U, N_ANCHOR, N_ANCHOR, N_ANCHOR,
                                     1.f, nullptr, 0.f, EPI_PLAIN, nullptr, nullptr);
            gemm_k<false><<<g, tb>>>(Zc, U, Za, N_ANCHOR, N_ANCHOR, N_ANCHOR,
                                     -1.f, Zc, 2.f, EPI_PLAIN, nullptr, nullptr);
            float* tmp = Zc; Zc = Za; Za = tmp;
        }
        Z = Zc;  // converged inverse
    }

    // 4) C = priv * pub^T
    {
        dim3 g((N_ANCHOR + BN - 1) / BN, (BDIM + BM - 1) / BM);
        gemm_k<true><<<g, tb>>>(priv, pub, Cm, BDIM, N_ANCHOR, PDIM,
                                1.f, nullptr, 0.f, EPI_PLAIN, nullptr, nullptr);
        // 5) X = C * Z   (~ C S^{-1})
        gemm_k<false><<<g, tb>>>(Cm, Z, X, BDIM, N_ANCHOR, N_ANCHOR,
                                 1.f, nullptr, 0.f, EPI_PLAIN, nullptr, nullptr);
        // 6) E = C - X S  (residual of the solve)
        gemm_k<false><<<g, tb>>>(X, S, E, BDIM, N_ANCHOR, N_ANCHOR,
                                 -1.f, Cm, 1.f, EPI_PLAIN, nullptr, nullptr);
        // 7) X2 = X + E Z (one iterative refinement -> fp32-accurate solve)
        gemm_k<false><<<g, tb>>>(E, Z, X2, BDIM, N_ANCHOR, N_ANCHOR,
                                 1.f, X, 1.f, EPI_PLAIN, nullptr, nullptr);
    }

    // 8) per-row clip scale: ||emb_i|| = sqrt(X2_i . C_i)
    scale_k<<<BDIM, 256>>>(N_ANCHOR);

    // 9) out = scale*T + clamp(priv - T, +-1e-3),  T = X2 * pub
    {
        dim3 g((PDIM + BN - 1) / BN, (BDIM + BM - 1) / BM);
        gemm_k<false><<<g, tb>>>(X2, pub, out, BDIM, PDIM, N_ANCHOR,
                                 1.f, nullptr, 0.f, EPI_CLAMP, priv, scale);
    }
}

// round 3
// speedup vs baseline: 1.0153x; 1.0153x over previous
#include <cuda_runtime.h>
#include <math.h>

// Problem dimensions (fixed by the dataset)
#define N_ANCHOR 1000
#define PDIM     100000
#define BDIM     256

// GEMM tiling
#define BM 64
#define BN 64
#define BK 16

#define EPI_PLAIN 0
#define EPI_SYM   1
#define EPI_CLAMP 2

#define NEWTON_ITERS 10

// ---------------- scratch (device globals; no allocation allowed) ----------
__device__ float g_S [N_ANCHOR * N_ANCHOR];
__device__ float g_Z [N_ANCHOR * N_ANCHOR];
__device__ float g_Z2[N_ANCHOR * N_ANCHOR];
__device__ float g_U [N_ANCHOR * N_ANCHOR];
__device__ float g_Cm[BDIM * N_ANCHOR];
__device__ float g_X [BDIM * N_ANCHOR];
__device__ float g_E [BDIM * N_ANCHOR];
__device__ float g_X2[BDIM * N_ANCHOR];
__device__ float g_rowsum[N_ANCHOR];
__device__ float g_invb;
__device__ float g_scale[BDIM];

// ---------------------------------------------------------------------------
// Generic tiled SGEMM, arbitrary M/N/K (k-tail handled with guards).
//   TB = true : C[M,N] = A[M,K] * B[N,K]^T        (both row-major, contract cols)
//   TB = false: C[M,N] = A[M,K] * B[K,N]
// Epilogue modes:
//   EPI_PLAIN: C = alpha*acc (+ beta*D)
//   EPI_SYM  : square symmetric output; only lower-tri blocks computed, mirrored
//   EPI_CLAMP: out = scale[m]*acc + clamp(priv[m,n] - acc, +-1e-3)
// ---------------------------------------------------------------------------
template <bool TB>
__global__ void __launch_bounds__(256)
gemm_k(const float* __restrict__ A, const float* __restrict__ B,
       float* __restrict__ C, int M, int N, int K,
       float alpha, const float* __restrict__ D, float beta,
       int mode, const float* __restrict__ priv, const float* __restrict__ scale)
{
    const int bx = blockIdx.x, by = blockIdx.y;
    if (mode == EPI_SYM && bx > by) return;  // upper-tri blocks filled by mirror

    const int n0 = bx * BN;
    const int m0 = by * BM;
    const int tx = threadIdx.x, ty = threadIdx.y;
    const int tid = ty * 16 + tx;

    __shared__ float As[BK][BM];
    __shared__ float Bs[BK][BN];

    float acc[4][4] = {};

    const int am  = tid >> 2;          // 0..63  (row within tile)
    const int ak  = (tid & 3) << 2;    // 0,4,8,12 (k within tile, vec4)
    const int bk  = tid >> 4;          // 0..15  (NN: k within tile)
    const int bn4 = (tid & 15) << 2;   // 0..60  (NN: col within tile, vec4)

    for (int k0 = 0; k0 < K; k0 += BK) {
        // ---- load A tile (vec4 along K, store transposed), k-guarded ----
        {
            float4 av = make_float4(0.f, 0.f, 0.f, 0.f);
            if (m0 + am < M) {
                const float* Arow = &A[(size_t)(m0 + am) * K + k0 + ak];
                if (k0 + ak + 3 < K) {
                    av = *(const float4*)Arow;
                } else {
                    float t[4] = {0.f, 0.f, 0.f, 0.f};
                    #pragma unroll
                    for (int j = 0; j < 4; j++)
                        if (k0 + ak + j < K) t[j] = Arow[j];
                    av = make_float4(t[0], t[1], t[2], t[3]);
                }
            }
            As[ak + 0][am] = av.x; As[ak + 1][am] = av.y;
            As[ak + 2][am] = av.z; As[ak + 3][am] = av.w;
        }

        // ---- load B tile, k-guarded ----
        if (TB) {
            float4 bv = make_float4(0.f, 0.f, 0.f, 0.f);
            if (n0 + am < N) {
                const float* Brow = &B[(size_t)(n0 + am) * K + k0 + ak];
                if (k0 + ak + 3 < K) {
                    bv = *(const float4*)Brow;
                } else {
                    float t[4] = {0.f, 0.f, 0.f, 0.f};
                    #pragma unroll
                    for (int j = 0; j < 4; j++)
                        if (k0 + ak + j < K) t[j] = Brow[j];
                    bv = make_float4(t[0], t[1], t[2], t[3]);
                }
            }
            Bs[ak + 0][am] = bv.x; Bs[ak + 1][am] = bv.y;
            Bs[ak + 2][am] = bv.z; Bs[ak + 3][am] = bv.w;
        } else {
            if (k0 + bk < K) {
                const float* Brow = &B[(size_t)(k0 + bk) * N + n0 + bn4];
                if (n0 + bn4 + 3 < N) {
                    *(float4*)&Bs[bk][bn4] = *(const float4*)Brow;
                } else {
                    #pragma unroll
                    for (int j = 0; j < 4; j++)
                        Bs[bk][bn4 + j] = (n0 + bn4 + j < N) ? Brow[j] : 0.f;
                }
            } else {
                *(float4*)&Bs[bk][bn4] = make_float4(0.f, 0.f, 0.f, 0.f);
            }
        }
        __syncthreads();

        // ---- compute ----
        #pragma unroll
        for (int k = 0; k < BK; k++) {
            float4 a = *(const float4*)&As[k][ty << 2];
            float4 b = *(const float4*)&Bs[k][tx << 2];
            float ar[4] = {a.x, a.y, a.z, a.w};
            float br[4] = {b.x, b.y, b.z, b.w};
            #pragma unroll
            for (int i = 0; i < 4; i++)
                #pragma unroll
                for (int j = 0; j < 4; j++)
                    acc[i][j] = fmaf(ar[i], br[j], acc[i][j]);
        }
        __syncthreads();
    }

    // ---- epilogue ----
    #pragma unroll
    for (int i = 0; i < 4; i++) {
        const int m = m0 + (ty << 2) + i;
        if (m >= M) continue;
        #pragma unroll
        for (int j = 0; j < 4; j++) {
            const int n = n0 + (tx << 2) + j;
            if (n >= N) continue;
            const float t = acc[i][j];
            float v;
            if (mode == EPI_CLAMP) {
                float r = priv[(size_t)m * N + n] - t;
                r = fminf(fmaxf(r, -1e-3f), 1e-3f);
                v = scale[m] * t + r;
            } else {
                v = alpha * t;
                if (D) v += beta * D[(size_t)m * N + n];
            }
            C[(size_t)m * N + n] = v;
            if (mode == EPI_SYM)
                C[(size_t)n * N + m] = v;   // mirror (bitwise-consistent on diag)
        }
    }
}

// ---------------- small helper kernels -------------------------------------
__global__ void rowsum_abs_k(int n)
{
    const int i = blockIdx.x;
    float s = 0.f;
    for (int j = threadIdx.x; j < n; j += blockDim.x) s += fabsf(g_S[i * n + j]);
    __shared__ float sh[256];
    sh[threadIdx.x] = s; __syncthreads();
    for (int o = 128; o > 0; o >>= 1) {
        if (threadIdx.x < o) sh[threadIdx.x] += sh[threadIdx.x + o];
        __syncthreads();
    }
    if (threadIdx.x == 0) g_rowsum[i] = sh[0];
}

__global__ void maxinv_k(int n)
{
    float m = 0.f;
    for (int j = threadIdx.x; j < n; j += blockDim.x) m = fmaxf(m, g_rowsum[j]);
    __shared__ float sh[256];
    sh[threadIdx.x] = m; __syncthreads();
    for (int o = 128; o > 0; o >>= 1) {
        if (threadIdx.x < o) sh[threadIdx.x] = fmaxf(sh[threadIdx.x], sh[threadIdx.x + o]);
        __syncthreads();
    }
    if (threadIdx.x == 0) g_invb = 1.0f / sh[0];
}

__global__ void initZ_k(int n)
{
    const int idx = blockIdx.x * blockDim.x + threadIdx.x;
    if (idx < n * n) {
        const int i = idx / n, j = idx % n;
        g_Z[idx] = (i == j) ? g_invb : 0.f;
    }
}

__global__ void scale_k(int n)
{
    const int i = blockIdx.x;
    float s = 0.f;
    for (int j = threadIdx.x; j < n; j += blockDim.x)
        s += g_X2[i * n + j] * g_Cm[i * n + j];   // = ||P_S priv_i||^2
    __shared__ float sh[256];
    sh[threadIdx.x] = s; __syncthreads();
    for (int o = 128; o > 0; o >>= 1) {
        if (threadIdx.x < o) sh[threadIdx.x] += sh[threadIdx.x + o];
        __syncthreads();
    }
    if (threadIdx.x == 0) {
        const float d = fmaxf(sh[0], 1e-30f);
        g_scale[i] = fminf(1.0f / sqrtf(d), 1.0f);   // CLIP = 1.0
    }
}

// ---------------------------------------------------------------------------
extern "C" void kernel_launch(void* const* d_in, const int* in_sizes, int n_in,
                              void* d_out, int out_size)
{
    const float* pub  = (const float*)d_in[0];   // [1000, 100000]
    const float* priv = (const float*)d_in[1];   // [256, 100000]
    // d_in[2] (L_init) and d_in[3] (power_iter) are mathematically irrelevant:
    // for power_iter >= 1 the output depends only on rowspace(pub_grad).
    float* out = (float*)d_out;                  // [256, 100000]

    float *S, *Z, *Z2, *U, *Cm, *X, *E, *X2, *scale;
    cudaGetSymbolAddress((void**)&S,  g_S);
    cudaGetSymbolAddress((void**)&Z,  g_Z);
    cudaGetSymbolAddress((void**)&Z2, g_Z2);
    cudaGetSymbolAddress((void**)&U,  g_U);
    cudaGetSymbolAddress((void**)&Cm, g_Cm);
    cudaGetSymbolAddress((void**)&X,  g_X);
    cudaGetSymbolAddress((void**)&E,  g_E);
    cudaGetSymbolAddress((void**)&X2, g_X2);
    cudaGetSymbolAddress((void**)&scale, g_scale);

    const dim3 tb(16, 16);

    // 1) S = pub * pub^T  (symmetric: lower-tri blocks + mirror)
    {
        dim3 g((N_ANCHOR + BN - 1) / BN, (N_ANCHOR + BM - 1) / BM);
        gemm_k<true><<<g, tb>>>(pub, pub, S, N_ANCHOR, N_ANCHOR, PDIM,
                                1.f, nullptr, 0.f, EPI_SYM, nullptr, nullptr);
    }

    // 2) spectral bound + Z0 = I / ||S||_1
    rowsum_abs_k<<<N_ANCHOR, 256>>>(N_ANCHOR);
    maxinv_k<<<1, 256>>>(N_ANCHOR);
    initZ_k<<<(N_ANCHOR * N_ANCHOR + 255) / 256, 256>>>(N_ANCHOR);

    // 3) Newton-Schulz: Z <- Z (2I - S Z)   (quadratic; kappa(S) ~ 1.5)
    {
        dim3 g((N_ANCHOR + BN - 1) / BN, (N_ANCHOR + BM - 1) / BM);
        float* Zc = Z;
        float* Za = Z2;
        for (int t = 0; t < NEWTON_ITERS; t++) {
            gemm_k<false><<<g, tb>>>(S, Zc, U, N_ANCHOR, N_ANCHOR, N_ANCHOR,
                                     1.f, nullptr, 0.f, EPI_PLAIN, nullptr, nullptr);
            gemm_k<false><<<g, tb>>>(Zc, U, Za, N_ANCHOR, N_ANCHOR, N_ANCHOR,
                                     -1.f, Zc, 2.f, EPI_PLAIN, nullptr, nullptr);
            float* tmp = Zc; Zc = Za; Za = tmp;
        }
        Z = Zc;  // converged inverse
    }

    // 4) C = priv * pub^T
    {
        dim3 g((N_ANCHOR + BN - 1) / BN, (BDIM + BM - 1) / BM);
        gemm_k<true><<<g, tb>>>(priv, pub, Cm, BDIM, N_ANCHOR, PDIM,
                                1.f, nullptr, 0.f, EPI_PLAIN, nullptr, nullptr);
        // 5) X = C * Z   (~ C S^{-1})
        gemm_k<false><<<g, tb>>>(Cm, Z, X, BDIM, N_ANCHOR, N_ANCHOR,
                                 1.f, nullptr, 0.f, EPI_PLAIN, nullptr, nullptr);
        // 6) E = C - X S  (residual of the solve)
        gemm_k<false><<<g, tb>>>(X, S, E, BDIM, N_ANCHOR, N_ANCHOR,
                                 -1.f, Cm, 1.f, EPI_PLAIN, nullptr, nullptr);
        // 7) X2 = X + E Z (one iterative refinement -> fp32-accurate solve)
        gemm_k<false><<<g, tb>>>(E, Z, X2, BDIM, N_ANCHOR, N_ANCHOR,
                                 1.f, X, 1.f, EPI_PLAIN, nullptr, nullptr);
    }

    // 8) per-row clip scale: ||emb_i|| = sqrt(X2_i . C_i)
    scale_k<<<BDIM, 256>>>(N_ANCHOR);

    // 9) out = scale*T + clamp(priv - T, +-1e-3),  T = X2 * pub
    {
        dim3 g((PDIM + BN - 1) / BN, (BDIM + BM - 1) / BM);
        gemm_k<false><<<g, tb>>>(X2, pub, out, BDIM, PDIM, N_ANCHOR,
                                 1.f, nullptr, 0.f, EPI_CLAMP, priv, scale);
    }
}

// round 5
// speedup vs baseline: 4.2932x; 4.2286x over previous
#include <cuda_runtime.h>
#include <cuda_bf16.h>
#include <cstdint>
#include <math.h>

#define NA 1000
#define KP 100000
#define BD 256
#define KPAD 1024
#define RICH_ITERS 14
#define POW_ITERS 8

// Tile geometry: CTA 128x128, BK=32, 8 warps (4m x 2n), warp tile 32x64.
// Smem per tile: 128 rows x 40 halves (32 data + 8 pad) = 10240 B.
// 4 tiles (Ah, Al, Bh, Bl) = 40960 B static shared.
#define TSTRIDE 40          // halves per smem row (80 bytes)
#define TILE_B  10240       // bytes per tile

// ---------------- device scratch ----------------
__device__ __align__(16) __nv_bfloat16 g_pubH[(size_t)NA * KP];
__device__ __align__(16) __nv_bfloat16 g_pubL[(size_t)NA * KP];
__device__ __align__(16) __nv_bfloat16 g_privH[(size_t)BD * KP];
__device__ __align__(16) __nv_bfloat16 g_privL[(size_t)BD * KP];
__device__ __align__(16) __nv_bfloat16 g_SH[NA * KPAD];
__device__ __align__(16) __nv_bfloat16 g_SL[NA * KPAD];
__device__ __align__(16) __nv_bfloat16 g_XH[BD * KPAD];
__device__ __align__(16) __nv_bfloat16 g_XL[BD * KPAD];
__device__ float g_S [NA * NA];
__device__ float g_Sp[4][NA * NA];
__device__ float g_Cm[BD * NA];
__device__ float g_Cp[8][BD * NA];
__device__ float g_X [BD * NA];
__device__ float g_v[NA], g_y[NA];
__device__ float g_lam, g_alpha;
__device__ float g_scale[BD];

// ---------------- PTX helpers (portable: sm_80+) ----------------
__device__ __forceinline__ uint32_t smem_u32(const void* p) {
    uint32_t a;
    asm("{ .reg .u64 t; cvta.to.shared.u64 t, %1; cvt.u32.u64 %0, t; }" : "=r"(a) : "l"(p));
    return a;
}
__device__ __forceinline__ void ldsm4(uint32_t addr, uint32_t& r0, uint32_t& r1,
                                      uint32_t& r2, uint32_t& r3) {
    asm volatile("ldmatrix.sync.aligned.m8n8.x4.shared.b16 {%0,%1,%2,%3}, [%4];"
                 : "=r"(r0), "=r"(r1), "=r"(r2), "=r"(r3) : "r"(addr));
}
__device__ __forceinline__ void mma16816(float* c, const uint32_t* a, const uint32_t* b) {
    asm volatile(
        "mma.sync.aligned.m16n8k16.row.col.f32.bf16.bf16.f32 "
        "{%0,%1,%2,%3}, {%4,%5,%6,%7}, {%8,%9}, {%0,%1,%2,%3};"
        : "+f"(c[0]), "+f"(c[1]), "+f"(c[2]), "+f"(c[3])
        : "r"(a[0]), "r"(a[1]), "r"(a[2]), "r"(a[3]), "r"(b[0]), "r"(b[1]));
}

// ---------------- tile loaders ----------------
// bf16 source, K-major rows; 512 uint4 per tile, 2 per thread.
__device__ __forceinline__ void ldt(const __nv_bfloat16* __restrict__ src, long long ld,
                                    int row0, int rows, int kb, char* dst) {
    #pragma unroll
    for (int i = 0; i < 2; i++) {
        int e = threadIdx.x + i * 256;       // 0..511
        int r = e >> 2, q = e & 3;           // row, 16B-chunk
        uint4 v = make_uint4(0, 0, 0, 0);
        if (row0 + r < rows)
            v = *(const uint4*)&src[(long long)(row0 + r) * ld + kb + q * 8];
        *(uint4*)(dst + r * 80 + q * 16) = v;
    }
}
// transposed fp32 source: B[n,k] = src[k, n] (src = pub [NA, KP]); inline hi/lo split.
__device__ __forceinline__ void ldtT(const float* __restrict__ src, int n0, int Nrows,
                                     int kb, char* dsth, char* dstl) {
    #pragma unroll
    for (int i = 0; i < 16; i++) {
        int idx = threadIdx.x + i * 256;     // 0..4095
        int k = idx >> 7, n = idx & 127;
        float v = 0.f;
        if (kb + k < NA && n0 + n < Nrows)
            v = src[(long long)(kb + k) * KP + n0 + n];
        __nv_bfloat16 h = __float2bfloat16(v);
        __nv_bfloat16 l = __float2bfloat16(v - __bfloat162float(h));
        int off = n * 80 + k * 2;
        *(__nv_bfloat16*)(dsth + off) = h;
        *(__nv_bfloat16*)(dstl + off) = l;
    }
}

// ---------------------------------------------------------------------------
// HMMA GEMM: D[m,n] = sum_k A[m,k]*B[n,k], bf16 hi/lo (3 passes), fp32 acc.
// BT=0: B from bf16 hi/lo arrays; BT=1: B transposed inline from fp32 pub.
// mode 0: partial store to outp + z*sliceStride
// mode 1: out = aux2[m]*t + clamp(aux[m,n]-t, +-1e-3)
// mode 2: outp[m,n] += alpha*(aux[m,n]-t)      (Richardson, in place)
// ---------------------------------------------------------------------------
template <int BT>
__global__ void __launch_bounds__(256, 2)
gemm_tc(const __nv_bfloat16* __restrict__ Ah, const __nv_bfloat16* __restrict__ Al,
        long long lda, int Mrows,
        const __nv_bfloat16* __restrict__ Bh, const __nv_bfloat16* __restrict__ Bl,
        const float* __restrict__ Bsrc, long long ldb, int Nrows,
        int K, int chunksPer,
        float* __restrict__ outp, long long sliceStride, long long ldc,
        int mode, const float* __restrict__ aux, long long ldaux,
        const float* __restrict__ aux2, const float* __restrict__ alphap, int tri)
{
    if (tri && blockIdx.x > blockIdx.y) return;
    const int m0 = blockIdx.y * 128, n0 = blockIdx.x * 128, z = blockIdx.z;
    const int kb0 = z * chunksPer * 32;
    const int kend = min(K, kb0 + chunksPer * 32);
    if (kb0 >= kend) return;
    const int nch = (kend - kb0) >> 5;        // K multiples of 32 by construction

    __shared__ __align__(16) char smem[4 * TILE_B];
    char* sAh = smem;
    char* sAl = smem + TILE_B;
    char* sBh = smem + 2 * TILE_B;
    char* sBl = smem + 3 * TILE_B;
    const uint32_t uAh = smem_u32(sAh), uAl = smem_u32(sAl);
    const uint32_t uBh = smem_u32(sBh), uBl = smem_u32(sBl);

    const int tid = threadIdx.x;
    const int lane = tid & 31, wid = tid >> 5;
    const int wm = wid >> 1, wn = wid & 1;

    float acc[2][8][4];
    #pragma unroll
    for (int i = 0; i < 2; i++)
        #pragma unroll
        for (int j = 0; j < 8; j++)
            #pragma unroll
            for (int q = 0; q < 4; q++) acc[i][j][q] = 0.f;

    // ldmatrix lane addressing (byte offsets into tile)
    const int aRow = wm * 32 + (lane & 15);
    const int aKof = (lane >> 4) * 8;
    const int bRowBase = wn * 64 + (lane & 7) + ((lane >> 4) << 3);
    const int bKof = ((lane >> 3) & 1) << 3;

    for (int c = 0; c < nch; c++) {
        const int kb = kb0 + c * 32;
        __syncthreads();
        ldt(Ah, lda, m0, Mrows, kb, sAh);
        ldt(Al, lda, m0, Mrows, kb, sAl);
        if (BT == 0) {
            ldt(Bh, ldb, n0, Nrows, kb, sBh);
            ldt(Bl, ldb, n0, Nrows, kb, sBl);
        } else {
            ldtT(Bsrc, n0, Nrows, kb, sBh, sBl);
        }
        __syncthreads();

        #pragma unroll
        for (int ks = 0; ks < 2; ks++) {
            uint32_t ah[2][4], al[2][4];
            #pragma unroll
            for (int mf = 0; mf < 2; mf++) {
                uint32_t ao = (uint32_t)((aRow + mf * 16) * 80 + (ks * 16 + aKof) * 2);
                ldsm4(uAh + ao, ah[mf][0], ah[mf][1], ah[mf][2], ah[mf][3]);
                ldsm4(uAl + ao, al[mf][0], al[mf][1], al[mf][2], al[mf][3]);
            }
            #pragma unroll
            for (int nf2 = 0; nf2 < 4; nf2++) {
                uint32_t bh[4], bl[4];
                uint32_t bo = (uint32_t)((bRowBase + nf2 * 16) * 80 + (ks * 16 + bKof) * 2);
                ldsm4(uBh + bo, bh[0], bh[1], bh[2], bh[3]);
                ldsm4(uBl + bo, bl[0], bl[1], bl[2], bl[3]);
                #pragma unroll
                for (int h = 0; h < 2; h++) {
                    const int nf = nf2 * 2 + h;
                    uint32_t* bhp = &bh[h * 2];
                    uint32_t* blp = &bl[h * 2];
                    #pragma unroll
                    for (int mf = 0; mf < 2; mf++) {
                        mma16816(acc[mf][nf], ah[mf], bhp);
                        mma16816(acc[mf][nf], ah[mf], blp);
                        mma16816(acc[mf][nf], al[mf], bhp);
                    }
                }
            }
        }
    }

    // epilogue: acc[mf][nf][{c0,c1 row, c2,c3 row+8}]
    float* po = outp + (size_t)z * (size_t)sliceStride;
    #pragma unroll
    for (int mf = 0; mf < 2; mf++) {
        #pragma unroll
        for (int hh = 0; hh < 2; hh++) {
            const int m = m0 + wm * 32 + mf * 16 + (lane >> 2) + hh * 8;
            if (m >= Mrows) continue;
            const float sc = (mode == 1) ? aux2[m] : 0.f;
            const float al = (mode == 2) ? *alphap : 0.f;
            #pragma unroll
            for (int nf = 0; nf < 8; nf++) {
                const int nb = n0 + wn * 64 + nf * 8 + (lane & 3) * 2;
                #pragma unroll
                for (int j = 0; j < 2; j++) {
                    const int n = nb + j;
                    if (n >= Nrows) continue;
                    const float t = acc[mf][nf][hh * 2 + j];
                    size_t ix = (size_t)m * ldc + n;
                    if (mode == 1) {
                        float rr = aux[(size_t)m * ldaux + n] - t;
                        rr = fminf(fmaxf(rr, -1e-3f), 1e-3f);
                        po[ix] = sc * t + rr;
                    } else if (mode == 2) {
                        po[ix] = po[ix] + al * (aux[(size_t)m * ldaux + n] - t);
                    } else {
                        po[ix] = t;
                    }
                }
            }
        }
    }
}

// ---------------- small kernels ----------------
__global__ void split_k(const float* __restrict__ s, __nv_bfloat16* __restrict__ h,
                        __nv_bfloat16* __restrict__ l, size_t n4) {
    size_t i = (size_t)blockIdx.x * blockDim.x + threadIdx.x;
    if (i < n4) {
        float4 v = ((const float4*)s)[i];
        float vv[4] = {v.x, v.y, v.z, v.w};
        #pragma unroll
        for (int j = 0; j < 4; j++) {
            __nv_bfloat16 hh = __float2bfloat16(vv[j]);
            h[i * 4 + j] = hh;
            l[i * 4 + j] = __float2bfloat16(vv[j] - __bfloat162float(hh));
        }
    }
}
__global__ void splitS_k() {
    int idx = blockIdx.x * blockDim.x + threadIdx.x;
    if (idx < NA * KPAD) {
        int i = idx >> 10, k = idx & 1023;
        float v = (k < NA) ? g_S[i * NA + k] : 0.f;
        __nv_bfloat16 h = __float2bfloat16(v);
        g_SH[idx] = h;
        g_SL[idx] = __float2bfloat16(v - __bfloat162float(h));
    }
}
__global__ void splitX_k() {
    int idx = blockIdx.x * blockDim.x + threadIdx.x;
    if (idx < BD * KPAD) {
        int i = idx >> 10, k = idx & 1023;
        float v = (k < NA) ? g_X[i * NA + k] : 0.f;
        __nv_bfloat16 h = __float2bfloat16(v);
        g_XH[idx] = h;
        g_XL[idx] = __float2bfloat16(v - __bfloat162float(h));
    }
}
__global__ void reduce_S_k() {
    int idx = blockIdx.x * blockDim.x + threadIdx.x;
    if (idx < NA * NA) {
        int i = idx / NA, j = idx % NA;
        if (i >= j) {
            float s = g_Sp[0][idx] + g_Sp[1][idx] + g_Sp[2][idx] + g_Sp[3][idx];
            g_S[i * NA + j] = s;
            g_S[j * NA + i] = s;
        }
    }
}
__global__ void reduce_C_k() {
    int idx = blockIdx.x * blockDim.x + threadIdx.x;
    if (idx < BD * NA) {
        float s = 0.f;
        #pragma unroll
        for (int zz = 0; zz < 8; zz++) s += g_Cp[zz][idx];
        g_Cm[idx] = s;
    }
}
__global__ void initv_k() {
    int j = blockIdx.x * blockDim.x + threadIdx.x;
    if (j < NA) g_v[j] = g_S[j];
}
__global__ void matvec_k() {
    const int i = blockIdx.x;
    float s = 0.f;
    for (int j = threadIdx.x; j < NA; j += 256) s += g_S[i * NA + j] * g_v[j];
    __shared__ float sh[256];
    sh[threadIdx.x] = s; __syncthreads();
    for (int o = 128; o > 0; o >>= 1) {
        if (threadIdx.x < o) sh[threadIdx.x] += sh[threadIdx.x + o];
        __syncthreads();
    }
    if (threadIdx.x == 0) g_y[i] = sh[0];
}
__global__ void vnorm_k() {
    __shared__ float sh[256]; __shared__ float lam;
    float s = 0.f;
    for (int j = threadIdx.x; j < NA; j += 256) { float y = g_y[j]; s += y * y; }
    sh[threadIdx.x] = s; __syncthreads();
    for (int o = 128; o > 0; o >>= 1) {
        if (threadIdx.x < o) sh[threadIdx.x] += sh[threadIdx.x + o];
        __syncthreads();
    }
    if (threadIdx.x == 0) { lam = sqrtf(sh[0]); g_lam = lam; }
    __syncthreads();
    for (int j = threadIdx.x; j < NA; j += 256) g_v[j] = g_y[j] / lam;
}
__global__ void alpha_k() { g_alpha = 1.2945f / g_lam; }
__global__ void initX_k() {
    int idx = blockIdx.x * blockDim.x + threadIdx.x;
    if (idx < BD * NA) g_X[idx] = g_alpha * g_Cm[idx];
}
__global__ void scale_k() {
    const int i = blockIdx.x;
    float s = 0.f;
    for (int j = threadIdx.x; j < NA; j += 256) s += g_X[i * NA + j] * g_Cm[i * NA + j];
    __shared__ float sh[256];
    sh[threadIdx.x] = s; __syncthreads();
    for (int o = 128; o > 0; o >>= 1) {
        if (threadIdx.x < o) sh[threadIdx.x] += sh[threadIdx.x + o];
        __syncthreads();
    }
    if (threadIdx.x == 0) {
        float d = fmaxf(sh[0], 1e-30f);
        g_scale[i] = fminf(rsqrtf(d), 1.0f);
    }
}

// ---------------------------------------------------------------------------
extern "C" void kernel_launch(void* const* d_in, const int* in_sizes, int n_in,
                              void* d_out, int out_size)
{
    const float* pub  = (const float*)d_in[0];
    const float* priv = (const float*)d_in[1];
    float* out = (float*)d_out;

    __nv_bfloat16 *pubH, *pubL, *privH, *privL, *SH, *SL, *XH, *XL;
    float *Sp, *Cm, *X, *scal, *alpha;
    cudaGetSymbolAddress((void**)&pubH, g_pubH);
    cudaGetSymbolAddress((void**)&pubL, g_pubL);
    cudaGetSymbolAddress((void**)&privH, g_privH);
    cudaGetSymbolAddress((void**)&privL, g_privL);
    cudaGetSymbolAddress((void**)&SH, g_SH);
    cudaGetSymbolAddress((void**)&SL, g_SL);
    cudaGetSymbolAddress((void**)&XH, g_XH);
    cudaGetSymbolAddress((void**)&XL, g_XL);
    cudaGetSymbolAddress((void**)&Sp, g_Sp);
    cudaGetSymbolAddress((void**)&Cm, g_Cm);
    cudaGetSymbolAddress((void**)&X, g_X);
    cudaGetSymbolAddress((void**)&scal, g_scale);
    cudaGetSymbolAddress((void**)&alpha, g_alpha);

    // 1) bf16 hi/lo splits
    {
        size_t n4 = (size_t)NA * KP / 4;
        split_k<<<(unsigned)((n4 + 255) / 256), 256>>>(pub, pubH, pubL, n4);
        n4 = (size_t)BD * KP / 4;
        split_k<<<(unsigned)((n4 + 255) / 256), 256>>>(priv, privH, privL, n4);
    }

    // 2) S = pub*pub^T (tri blocks + split-K 4)
    gemm_tc<0><<<dim3(8, 8, 4), 256>>>(
        pubH, pubL, KP, NA, pubH, pubL, nullptr, KP, NA,
        KP, 782, Sp, (long long)NA * NA, NA, 0, nullptr, 0, nullptr, nullptr, 1);
    reduce_S_k<<<(NA * NA + 255) / 256, 256>>>();
    splitS_k<<<(NA * KPAD + 255) / 256, 256>>>();

    // 3) C = priv*pub^T (split-K 8)
    gemm_tc<0><<<dim3(8, 2, 8), 256>>>(
        privH, privL, KP, BD, pubH, pubL, nullptr, KP, NA,
        KP, 391, (float*)Cm, 0, NA, 0, nullptr, 0, nullptr, nullptr, 0);
    // (split-K partials for C actually go to Cp)
    // NOTE: sliceStride=0 would overwrite; use Cp properly:
    {
        float* Cp;
        cudaGetSymbolAddress((void**)&Cp, g_Cp);
        gemm_tc<0><<<dim3(8, 2, 8), 256>>>(
            privH, privL, KP, BD, pubH, pubL, nullptr, KP, NA,
            KP, 391, Cp, (long long)BD * NA, NA, 0, nullptr, 0, nullptr, nullptr, 0);
        reduce_C_k<<<(BD * NA + 255) / 256, 256>>>();
    }

    // 4) lambda_max by power iteration; alpha = 1.2945/lam
    initv_k<<<4, 256>>>();
    for (int t = 0; t < POW_ITERS; t++) {
        matvec_k<<<NA, 256>>>();
        vnorm_k<<<1, 256>>>();
    }
    alpha_k<<<1, 1>>>();

    // 5) Richardson: X <- X + alpha*(C - X*S)
    initX_k<<<(BD * NA + 255) / 256, 256>>>();
    for (int t = 0; t < RICH_ITERS; t++) {
        splitX_k<<<(BD * KPAD + 255) / 256, 256>>>();
        gemm_tc<0><<<dim3(8, 2, 1), 256>>>(
            XH, XL, KPAD, BD, SH, SL, nullptr, KPAD, NA,
            KPAD, 32, X, 0, NA, 2, Cm, NA, nullptr, alpha, 0);
    }
    splitX_k<<<(BD * KPAD + 255) / 256, 256>>>();

    // 6) clip scale: ||emb_i||^2 = X_i . C_i
    scale_k<<<BD, 256>>>();

    // 7) out = scale*T + clamp(priv - T, +-1e-3), T = X*pub (B transposed inline)
    gemm_tc<1><<<dim3(782, 2, 1), 256>>>(
        XH, XL, KPAD, BD, nullptr, nullptr, pub, KP, KP,
        KPAD, 32, out, 0, KP, 1, priv, KP, scal, nullptr, 0);
}

// round 8
// speedup vs baseline: 7.6904x; 1.7913x over previous
#include <cuda_runtime.h>
#include <cuda_bf16.h>
#include <cstdint>
#include <math.h>

#define NA 1000
#define KP 100000
#define BD 256
#define KPAD 1024
#define RICH_ITERS 11
#define POW_ITERS 6

// Tile: CTA 128x128, BK=32, 8 warps (4m x 2n), warp tile 32x64.
// Smem tile: 128 rows x 40 halves (32 data + 8 pad) = 10240 B; 4 tiles/stage.
#define TILE_B  10240
#define STAGE_B (4 * TILE_B)   // 40960

// ---------------- device scratch ----------------
__device__ __align__(16) __nv_bfloat16 g_pubH[(size_t)NA * KP];
__device__ __align__(16) __nv_bfloat16 g_pubL[(size_t)NA * KP];
__device__ __align__(16) __nv_bfloat16 g_privH[(size_t)BD * KP];
__device__ __align__(16) __nv_bfloat16 g_privL[(size_t)BD * KP];
__device__ __align__(16) __nv_bfloat16 g_SH[NA * KPAD];
__device__ __align__(16) __nv_bfloat16 g_SL[NA * KPAD];
__device__ __align__(16) __nv_bfloat16 g_XH0[BD * KPAD];
__device__ __align__(16) __nv_bfloat16 g_XL0[BD * KPAD];
__device__ __align__(16) __nv_bfloat16 g_XH1[BD * KPAD];
__device__ __align__(16) __nv_bfloat16 g_XL1[BD * KPAD];
__device__ float g_S [NA * NA];
__device__ float g_Sp[8][NA * NA];
__device__ float g_Cm[BD * NA];
__device__ float g_Cp[16][BD * NA];
__device__ float g_X [BD * NA];
__device__ float g_v[NA], g_y[NA];
__device__ float g_lam, g_alpha;
__device__ float g_scale[BD];

// ---------------- PTX helpers ----------------
__device__ __forceinline__ uint32_t smem_u32(const void* p) {
    uint32_t a;
    asm("{ .reg .u64 t; cvta.to.shared.u64 t, %1; cvt.u32.u64 %0, t; }" : "=r"(a) : "l"(p));
    return a;
}
__device__ __forceinline__ void ldsm4(uint32_t addr, uint32_t& r0, uint32_t& r1,
                                      uint32_t& r2, uint32_t& r3) {
    asm volatile("ldmatrix.sync.aligned.m8n8.x4.shared.b16 {%0,%1,%2,%3}, [%4];"
                 : "=r"(r0), "=r"(r1), "=r"(r2), "=r"(r3) : "r"(addr));
}
__device__ __forceinline__ void mma16816(float* c, const uint32_t* a, const uint32_t* b) {
    asm volatile(
        "mma.sync.aligned.m16n8k16.row.col.f32.bf16.bf16.f32 "
        "{%0,%1,%2,%3}, {%4,%5,%6,%7}, {%8,%9}, {%0,%1,%2,%3};"
        : "+f"(c[0]), "+f"(c[1]), "+f"(c[2]), "+f"(c[3])
        : "r"(a[0]), "r"(a[1]), "r"(a[2]), "r"(a[3]), "r"(b[0]), "r"(b[1]));
}
__device__ __forceinline__ void cpa16(uint32_t dst, const void* src, int srcsz) {
    asm volatile("cp.async.ca.shared.global [%0], [%1], 16, %2;"
                 :: "r"(dst), "l"(src), "r"(srcsz));
}
#define CP_COMMIT() asm volatile("cp.async.commit_group;" ::: "memory")

// ---------------- tile loaders ----------------
// async: bf16 K-major rows; 512 uint4 per tile, 2 per thread.
__device__ __forceinline__ void ldt_async(const __nv_bfloat16* __restrict__ src, long long ld,
                                          int row0, int rows, int kb, uint32_t dst) {
    #pragma unroll
    for (int i = 0; i < 2; i++) {
        int e = threadIdx.x + i * 256;
        int r = e >> 2, q = e & 3;
        int gr = row0 + r;
        int sz = (gr < rows) ? 16 : 0;
        int rr = (gr < rows) ? gr : (rows - 1);
        cpa16(dst + r * 80 + q * 16, &src[(long long)rr * ld + kb + q * 8], sz);
    }
}
// sync transposed fp32: B[n,k] = src[k, n0+n]; inline hi/lo split.
__device__ __forceinline__ void ldtT(const float* __restrict__ src, int n0, int Nrows,
                                     int kb, char* dsth, char* dstl) {
    #pragma unroll
    for (int i = 0; i < 16; i++) {
        int idx = threadIdx.x + i * 256;
        int k = idx >> 7, n = idx & 127;
        float v = 0.f;
        if (kb + k < NA && n0 + n < Nrows)
            v = src[(long long)(kb + k) * KP + n0 + n];
        __nv_bfloat16 h = __float2bfloat16(v);
        __nv_bfloat16 l = __float2bfloat16(v - __bfloat162float(h));
        int off = n * 80 + k * 2;
        *(__nv_bfloat16*)(dsth + off) = h;
        *(__nv_bfloat16*)(dstl + off) = l;
    }
}

// ---------------------------------------------------------------------------
// HMMA GEMM: D[m,n] = sum_k A[m,k]*B[n,k], bf16 hi/lo (3 passes), fp32 acc.
// BT=0: B from bf16 arrays, cp.async double-buffered (dyn smem 2*STAGE_B).
// BT=1: B transposed inline from fp32 (dyn smem STAGE_B), sync loads.
// mode 0: partial store to outp + z*sliceStride
// mode 1: out = aux2[m]*t + clamp(aux[m,n]-t, +-1e-3)
// mode 2: xnew = outp[m,n] + alpha*(aux[m,n]-t); store fp32 + bf16 split ping-pong
// ---------------------------------------------------------------------------
template <int BT>
__global__ void __launch_bounds__(256, 2)
gemm_tc(const __nv_bfloat16* __restrict__ Ah, const __nv_bfloat16* __restrict__ Al,
        long long lda, int Mrows,
        const __nv_bfloat16* __restrict__ Bh, const __nv_bfloat16* __restrict__ Bl,
        const float* __restrict__ Bsrc, long long ldb, int Nrows,
        int K, int chunksPer,
        float* __restrict__ outp, long long sliceStride, long long ldc,
        int mode, const float* __restrict__ aux, long long ldaux,
        const float* __restrict__ aux2, const float* __restrict__ alphap, int tri,
        __nv_bfloat16* __restrict__ xoH, __nv_bfloat16* __restrict__ xoL)
{
    if (tri && blockIdx.x > blockIdx.y) return;
    const int m0 = blockIdx.y * 128, n0 = blockIdx.x * 128, z = blockIdx.z;
    const int kb0 = z * chunksPer * 32;
    const int kend = min(K, kb0 + chunksPer * 32);
    if (kb0 >= kend) return;
    const int nch = (kend - kb0) >> 5;

    extern __shared__ __align__(16) char smem[];
    const uint32_t sbase = smem_u32(smem);

    const int tid = threadIdx.x;
    const int lane = tid & 31, wid = tid >> 5;
    const int wm = wid >> 1, wn = wid & 1;

    float acc[2][8][4];
    #pragma unroll
    for (int i = 0; i < 2; i++)
        #pragma unroll
        for (int j = 0; j < 8; j++)
            #pragma unroll
            for (int q = 0; q < 4; q++) acc[i][j][q] = 0.f;

    const int aRow = wm * 32 + (lane & 15);
    const int aKof = (lane >> 4) * 8;
    const int bRowBase = wn * 64 + (lane & 7) + ((lane >> 4) << 3);
    const int bKof = ((lane >> 3) & 1) << 3;

    if (BT == 0) {
        // prologue: stage 0
        {
            const int kb = kb0;
            ldt_async(Ah, lda, m0, Mrows, kb, sbase);
            ldt_async(Al, lda, m0, Mrows, kb, sbase + TILE_B);
            ldt_async(Bh, ldb, n0, Nrows, kb, sbase + 2 * TILE_B);
            ldt_async(Bl, ldb, n0, Nrows, kb, sbase + 3 * TILE_B);
            CP_COMMIT();
        }
        for (int c = 0; c < nch; c++) {
            if (c + 1 < nch) {
                const int kb = kb0 + (c + 1) * 32;
                const uint32_t st = sbase + ((c + 1) & 1) * STAGE_B;
                ldt_async(Ah, lda, m0, Mrows, kb, st);
                ldt_async(Al, lda, m0, Mrows, kb, st + TILE_B);
                ldt_async(Bh, ldb, n0, Nrows, kb, st + 2 * TILE_B);
                ldt_async(Bl, ldb, n0, Nrows, kb, st + 3 * TILE_B);
                CP_COMMIT();
                asm volatile("cp.async.wait_group 1;" ::: "memory");
            } else {
                asm volatile("cp.async.wait_group 0;" ::: "memory");
            }
            __syncthreads();

            const uint32_t uS = sbase + (c & 1) * STAGE_B;
            const uint32_t uAh = uS, uAl = uS + TILE_B;
            const uint32_t uBh = uS + 2 * TILE_B, uBl = uS + 3 * TILE_B;
            #pragma unroll
            for (int ks = 0; ks < 2; ks++) {
                uint32_t ah[2][4], al[2][4];
                #pragma unroll
                for (int mf = 0; mf < 2; mf++) {
                    uint32_t ao = (uint32_t)((aRow + mf * 16) * 80 + (ks * 16 + aKof) * 2);
                    ldsm4(uAh + ao, ah[mf][0], ah[mf][1], ah[mf][2], ah[mf][3]);
                    ldsm4(uAl + ao, al[mf][0], al[mf][1], al[mf][2], al[mf][3]);
                }
                #pragma unroll
                for (int nf2 = 0; nf2 < 4; nf2++) {
                    uint32_t bh[4], bl[4];
                    uint32_t bo = (uint32_t)((bRowBase + nf2 * 16) * 80 + (ks * 16 + bKof) * 2);
                    ldsm4(uBh + bo, bh[0], bh[1], bh[2], bh[3]);
                    ldsm4(uBl + bo, bl[0], bl[1], bl[2], bl[3]);
                    #pragma unroll
                    for (int h = 0; h < 2; h++) {
                        const int nf = nf2 * 2 + h;
                        uint32_t* bhp = &bh[h * 2];
                        uint32_t* blp = &bl[h * 2];
                        #pragma unroll
                        for (int mf = 0; mf < 2; mf++) {
                            mma16816(acc[mf][nf], ah[mf], bhp);
                            mma16816(acc[mf][nf], ah[mf], blp);
                            mma16816(acc[mf][nf], al[mf], bhp);
                        }
                    }
                }
            }
            __syncthreads();
        }
    } else {
        char* sAh = smem;
        char* sAl = smem + TILE_B;
        char* sBh = smem + 2 * TILE_B;
        char* sBl = smem + 3 * TILE_B;
        const uint32_t uAh = sbase, uAl = sbase + TILE_B;
        const uint32_t uBh = sbase + 2 * TILE_B, uBl = sbase + 3 * TILE_B;
        for (int c = 0; c < nch; c++) {
            const int kb = kb0 + c * 32;
            __syncthreads();
            // sync A loads (bf16)
            #pragma unroll
            for (int i = 0; i < 2; i++) {
                int e = threadIdx.x + i * 256;
                int r = e >> 2, q = e & 3;
                uint4 vh = make_uint4(0, 0, 0, 0), vl = make_uint4(0, 0, 0, 0);
                if (m0 + r < Mrows) {
                    vh = *(const uint4*)&Ah[(long long)(m0 + r) * lda + kb + q * 8];
                    vl = *(const uint4*)&Al[(long long)(m0 + r) * lda + kb + q * 8];
                }
                *(uint4*)(sAh + r * 80 + q * 16) = vh;
                *(uint4*)(sAl + r * 80 + q * 16) = vl;
            }
            ldtT(Bsrc, n0, Nrows, kb, sBh, sBl);
            __syncthreads();

            #pragma unroll
            for (int ks = 0; ks < 2; ks++) {
                uint32_t ah[2][4], al[2][4];
                #pragma unroll
                for (int mf = 0; mf < 2; mf++) {
                    uint32_t ao = (uint32_t)((aRow + mf * 16) * 80 + (ks * 16 + aKof) * 2);
                    ldsm4(uAh + ao, ah[mf][0], ah[mf][1], ah[mf][2], ah[mf][3]);
                    ldsm4(uAl + ao, al[mf][0], al[mf][1], al[mf][2], al[mf][3]);
                }
                #pragma unroll
                for (int nf2 = 0; nf2 < 4; nf2++) {
                    uint32_t bh[4], bl[4];
                    uint32_t bo = (uint32_t)((bRowBase + nf2 * 16) * 80 + (ks * 16 + bKof) * 2);
                    ldsm4(uBh + bo, bh[0], bh[1], bh[2], bh[3]);
                    ldsm4(uBl + bo, bl[0], bl[1], bl[2], bl[3]);
                    #pragma unroll
                    for (int h = 0; h < 2; h++) {
                        const int nf = nf2 * 2 + h;
                        uint32_t* bhp = &bh[h * 2];
                        uint32_t* blp = &bl[h * 2];
                        #pragma unroll
                        for (int mf = 0; mf < 2; mf++) {
                            mma16816(acc[mf][nf], ah[mf], bhp);
                            mma16816(acc[mf][nf], ah[mf], blp);
                            mma16816(acc[mf][nf], al[mf], bhp);
                        }
                    }
                }
            }
        }
    }

    // ---- epilogue ----
    float* po = outp + (size_t)z * (size_t)sliceStride;
    #pragma unroll
    for (int mf = 0; mf < 2; mf++) {
        #pragma unroll
        for (int hh = 0; hh < 2; hh++) {
            const int m = m0 + wm * 32 + mf * 16 + (lane >> 2) + hh * 8;
            if (m >= Mrows) continue;
            const float sc = (mode == 1) ? aux2[m] : 0.f;
            const float al = (mode == 2) ? *alphap : 0.f;
            #pragma unroll
            for (int nf = 0; nf < 8; nf++) {
                const int nb = n0 + wn * 64 + nf * 8 + (lane & 3) * 2;
                #pragma unroll
                for (int j = 0; j < 2; j++) {
                    const int n = nb + j;
                    if (n >= Nrows) continue;
                    const float t = acc[mf][nf][hh * 2 + j];
                    size_t ix = (size_t)m * ldc + n;
                    if (mode == 1) {
                        float rr = aux[(size_t)m * ldaux + n] - t;
                        rr = fminf(fmaxf(rr, -1e-3f), 1e-3f);
                        po[ix] = sc * t + rr;
                    } else if (mode == 2) {
                        float xnew = po[ix] + al * (aux[(size_t)m * ldaux + n] - t);
                        po[ix] = xnew;
                        __nv_bfloat16 h = __float2bfloat16(xnew);
                        xoH[(size_t)m * KPAD + n] = h;
                        xoL[(size_t)m * KPAD + n] = __float2bfloat16(xnew - __bfloat162float(h));
                    } else {
                        po[ix] = t;
                    }
                }
            }
        }
    }
}

// ---------------- small kernels ----------------
__global__ void split_k(const float* __restrict__ s, __nv_bfloat16* __restrict__ h,
                        __nv_bfloat16* __restrict__ l, size_t n4) {
    size_t i = (size_t)blockIdx.x * blockDim.x + threadIdx.x;
    if (i < n4) {
        float4 v = ((const float4*)s)[i];
        float vv[4] = {v.x, v.y, v.z, v.w};
        #pragma unroll
        for (int j = 0; j < 4; j++) {
            __nv_bfloat16 hh = __float2bfloat16(vv[j]);
            h[i * 4 + j] = hh;
            l[i * 4 + j] = __float2bfloat16(vv[j] - __bfloat162float(hh));
        }
    }
}
__global__ void splitS_k() {
    int idx = blockIdx.x * blockDim.x + threadIdx.x;
    if (idx < NA * KPAD) {
        int i = idx >> 10, k = idx & 1023;
        float v = (k < NA) ? g_S[i * NA + k] : 0.f;
        __nv_bfloat16 h = __float2bfloat16(v);
        g_SH[idx] = h;
        g_SL[idx] = __float2bfloat16(v - __bfloat162float(h));
    }
}
__global__ void reduce_S_k() {
    int idx = blockIdx.x * blockDim.x + threadIdx.x;
    if (idx < NA * NA) {
        int i = idx / NA, j = idx % NA;
        if (i >= j) {
            float s = 0.f;
            #pragma unroll
            for (int zz = 0; zz < 8; zz++) s += g_Sp[zz][idx];
            g_S[i * NA + j] = s;
            g_S[j * NA + i] = s;
        }
    }
}
__global__ void reduce_C_k() {
    int idx = blockIdx.x * blockDim.x + threadIdx.x;
    if (idx < BD * NA) {
        float s = 0.f;
        #pragma unroll
        for (int zz = 0; zz < 16; zz++) s += g_Cp[zz][idx];
        g_Cm[idx] = s;
    }
}
__global__ void initv_k() {
    int j = blockIdx.x * blockDim.x + threadIdx.x;
    if (j < NA) g_v[j] = g_S[j];
}
__global__ void matvec_k() {
    const int i = blockIdx.x;
    float s = 0.f;
    for (int j = threadIdx.x; j < NA; j += 256) s += g_S[i * NA + j] * g_v[j];
    __shared__ float sh[256];
    sh[threadIdx.x] = s; __syncthreads();
    for (int o = 128; o > 0; o >>= 1) {
        if (threadIdx.x < o) sh[threadIdx.x] += sh[threadIdx.x + o];
        __syncthreads();
    }
    if (threadIdx.x == 0) g_y[i] = sh[0];
}
__global__ void vnorm_k() {
    __shared__ float sh[256]; __shared__ float lam;
    float s = 0.f;
    for (int j = threadIdx.x; j < NA; j += 256) { float y = g_y[j]; s += y * y; }
    sh[threadIdx.x] = s; __syncthreads();
    for (int o = 128; o > 0; o >>= 1) {
        if (threadIdx.x < o) sh[threadIdx.x] += sh[threadIdx.x + o];
        __syncthreads();
    }
    if (threadIdx.x == 0) { lam = sqrtf(sh[0]); g_lam = lam; }
    __syncthreads();
    for (int j = threadIdx.x; j < NA; j += 256) g_v[j] = g_y[j] / lam;
}
__global__ void alpha_k() { g_alpha = 1.25f / g_lam; }
// X0 = alpha*C, with fused bf16 split into ping buffer 0
__global__ void initX_k() {
    int idx = blockIdx.x * blockDim.x + threadIdx.x;
    if (idx < BD * NA) {
        int m = idx / NA, n = idx % NA;
        float v = g_alpha * g_Cm[idx];
        g_X[idx] = v;
        __nv_bfloat16 h = __float2bfloat16(v);
        g_XH0[(size_t)m * KPAD + n] = h;
        g_XL0[(size_t)m * KPAD + n] = __float2bfloat16(v - __bfloat162float(h));
    }
}
__global__ void scale_k() {
    const int i = blockIdx.x;
    float s = 0.f;
    for (int j = threadIdx.x; j < NA; j += 256) s += g_X[i * NA + j] * g_Cm[i * NA + j];
    __shared__ float sh[256];
    sh[threadIdx.x] = s; __syncthreads();
    for (int o = 128; o > 0; o >>= 1) {
        if (threadIdx.x < o) sh[threadIdx.x] += sh[threadIdx.x + o];
        __syncthreads();
    }
    if (threadIdx.x == 0) {
        float d = fmaxf(sh[0], 1e-30f);
        g_scale[i] = fminf(rsqrtf(d), 1.0f);
    }
}

// ---------------------------------------------------------------------------
extern "C" void kernel_launch(void* const* d_in, const int* in_sizes, int n_in,
                              void* d_out, int out_size)
{
    const float* pub  = (const float*)d_in[0];
    const float* priv = (const float*)d_in[1];
    float* out = (float*)d_out;

    cudaFuncSetAttribute(gemm_tc<0>, cudaFuncAttributeMaxDynamicSharedMemorySize, 2 * STAGE_B);
    cudaFuncSetAttribute(gemm_tc<1>, cudaFuncAttributeMaxDynamicSharedMemorySize, STAGE_B);

    __nv_bfloat16 *pubH, *pubL, *privH, *privL, *SH, *SL, *XH0, *XL0, *XH1, *XL1;
    float *Sp, *Cp, *Cm, *X, *scal, *alpha;
    cudaGetSymbolAddress((void**)&pubH, g_pubH);
    cudaGetSymbolAddress((void**)&pubL, g_pubL);
    cudaGetSymbolAddress((void**)&privH, g_privH);
    cudaGetSymbolAddress((void**)&privL, g_privL);
    cudaGetSymbolAddress((void**)&SH, g_SH);
    cudaGetSymbolAddress((void**)&SL, g_SL);
    cudaGetSymbolAddress((void**)&XH0, g_XH0);
    cudaGetSymbolAddress((void**)&XL0, g_XL0);
    cudaGetSymbolAddress((void**)&XH1, g_XH1);
    cudaGetSymbolAddress((void**)&XL1, g_XL1);
    cudaGetSymbolAddress((void**)&Sp, g_Sp);
    cudaGetSymbolAddress((void**)&Cp, g_Cp);
    cudaGetSymbolAddress((void**)&Cm, g_Cm);
    cudaGetSymbolAddress((void**)&X, g_X);
    cudaGetSymbolAddress((void**)&scal, g_scale);
    cudaGetSymbolAddress((void**)&alpha, g_alpha);

    // 1) bf16 hi/lo splits
    {
        size_t n4 = (size_t)NA * KP / 4;
        split_k<<<(unsigned)((n4 + 255) / 256), 256>>>(pub, pubH, pubL, n4);
        n4 = (size_t)BD * KP / 4;
        split_k<<<(unsigned)((n4 + 255) / 256), 256>>>(priv, privH, privL, n4);
    }

    // 2) S = pub*pub^T (tri blocks, split-K 8 -> 288 active CTAs)
    gemm_tc<0><<<dim3(8, 8, 8), 256, 2 * STAGE_B>>>(
        pubH, pubL, KP, NA, pubH, pubL, nullptr, KP, NA,
        KP, 391, Sp, (long long)NA * NA, NA, 0, nullptr, 0, nullptr, nullptr, 1,
        nullptr, nullptr);
    reduce_S_k<<<(NA * NA + 255) / 256, 256>>>();
    splitS_k<<<(NA * KPAD + 255) / 256, 256>>>();

    // 3) C = priv*pub^T (split-K 16 -> 256 CTAs)
    gemm_tc<0><<<dim3(8, 2, 16), 256, 2 * STAGE_B>>>(
        privH, privL, KP, BD, pubH, pubL, nullptr, KP, NA,
        KP, 196, Cp, (long long)BD * NA, NA, 0, nullptr, 0, nullptr, nullptr, 0,
        nullptr, nullptr);
    reduce_C_k<<<(BD * NA + 255) / 256, 256>>>();

    // 4) lambda_max via power iteration; alpha = 1.25/lam
    initv_k<<<4, 256>>>();
    for (int t = 0; t < POW_ITERS; t++) {
        matvec_k<<<NA, 256>>>();
        vnorm_k<<<1, 256>>>();
    }
    alpha_k<<<1, 1>>>();

    // 5) Richardson with fused re-split (ping-pong): X <- X + alpha*(C - X*S)
    initX_k<<<(BD * NA + 255) / 256, 256>>>();
    for (int t = 0; t < RICH_ITERS; t++) {
        __nv_bfloat16* inH  = (t & 1) ? XH1 : XH0;
        __nv_bfloat16* inL  = (t & 1) ? XL1 : XL0;
        __nv_bfloat16* outH = (t & 1) ? XH0 : XH1;
        __nv_bfloat16* outL = (t & 1) ? XL0 : XL1;
        gemm_tc<0><<<dim3(8, 2, 1), 256, 2 * STAGE_B>>>(
            inH, inL, KPAD, BD, SH, SL, nullptr, KPAD, NA,
            KPAD, 32, X, 0, NA, 2, Cm, NA, nullptr, alpha, 0, outH, outL);
    }
    __nv_bfloat16* finH = (RICH_ITERS & 1) ? XH1 : XH0;
    __nv_bfloat16* finL = (RICH_ITERS & 1) ? XL1 : XL0;

    // 6) clip scale: ||emb_i||^2 = X_i . C_i
    scale_k<<<BD, 256>>>();

    // 7) out = scale*T + clamp(priv - T, +-1e-3), T = X*pub (B transposed inline)
    gemm_tc<1><<<dim3(782, 2, 1), 256, STAGE_B>>>(
        finH, finL, KPAD, BD, nullptr, nullptr, pub, KP, KP,
        KPAD, 32, out, 0, KP, 1, priv, KP, scal, nullptr, 0,
        nullptr, nullptr);
}